// round 5
// baseline (speedup 1.0000x reference)
#include <cuda_runtime.h>
#include <cstdint>

#define DINLINE __device__ __forceinline__

// ---------------- problem sizes ----------------
#define M_DIM 512
#define N_DIM 4096
#define K_DIM 4096

// ---------------- GEMM tiling ----------------
#define BM 64
#define BN 128
#define BK 128                       // fp8 elements per K-chunk (4 k32 steps)
#define ROWB 144                     // padded smem row stride -> conflict-free ldmatrix
#define STAGES 4
#define KIT (K_DIM / BK)             // 32
#define TILE_A_BYTES (BM * ROWB)     // 9216
#define TILE_B_BYTES (BN * ROWB)     // 18432
#define STAGE_BYTES (TILE_A_BYTES + TILE_B_BYTES)   // 27648
#define SMEM_TOTAL (STAGES * STAGE_BYTES)           // 110592 -> 2 CTAs/SM

// ---------------- amax/quantize grids (exact cover) ----------------
#define AMAX_X_BLOCKS 256
#define AMAX_W_BLOCKS 2048
#define QUANT_X_BLOCKS 512
#define QUANT_W_BLOCKS 4096

// ---------------- scratch (static device globals; no allocs allowed) ----------------
// codes: e4m3 encodings of 2*e2m1 codebook value, i.e. {0,1,2,3,4,6,8,12} signed
__device__ __align__(256) uint8_t g_xq[M_DIM * K_DIM];   // 2 MB
__device__ __align__(256) uint8_t g_wq[N_DIM * K_DIM];   // 16 MB
__device__ unsigned int g_amax_bits[2];

// ---------------- PTX helpers ----------------
DINLINE uint32_t smem_u32(const void* p) {
    uint32_t a;
    asm("{ .reg .u64 t; cvta.to.shared.u64 t, %1; cvt.u32.u64 %0, t; }" : "=r"(a) : "l"(p));
    return a;
}

DINLINE void cp16(uint32_t dst, const void* src) {
    asm volatile("cp.async.cg.shared.global [%0], [%1], 16;" :: "r"(dst), "l"(src));
}
DINLINE void cp_commit() { asm volatile("cp.async.commit_group;" ::: "memory"); }

DINLINE void ldsm4(uint32_t* r, uint32_t addr) {
    asm volatile("ldmatrix.sync.aligned.m8n8.x4.shared.b16 {%0,%1,%2,%3}, [%4];"
                 : "=r"(r[0]), "=r"(r[1]), "=r"(r[2]), "=r"(r[3]) : "r"(addr));
}

// fp8 e4m3 MMA, f32 accumulate.
DINLINE void mma_f8(float* c, const uint32_t* a, const uint32_t* b) {
    asm volatile(
        "mma.sync.aligned.m16n8k32.row.col.f32.e4m3.e4m3.f32 "
        "{%0,%1,%2,%3}, {%4,%5,%6,%7}, {%8,%9}, {%0,%1,%2,%3};"
        : "+f"(c[0]), "+f"(c[1]), "+f"(c[2]), "+f"(c[3])
        : "r"(a[0]), "r"(a[1]), "r"(a[2]), "r"(a[3]), "r"(b[0]), "r"(b[1]));
}

// ---------------- phase 0: init ----------------
__global__ void init_kernel() {
    if (threadIdx.x == 0) { g_amax_bits[0] = 0u; g_amax_bits[1] = 0u; }
}

// ---------------- phase 1: fused amax (exact fp32 max of |t|), MLP=8 ----------------
__global__ void __launch_bounds__(256) amax_kernel(const float4* __restrict__ x,
                                                   const float4* __restrict__ w) {
    const float4* in;
    int which;
    if (blockIdx.x < AMAX_X_BLOCKS) {
        in = x + (size_t)blockIdx.x * 2048;
        which = 0;
    } else {
        in = w + (size_t)(blockIdx.x - AMAX_X_BLOCKS) * 2048;
        which = 1;
    }
    float4 v[8];
#pragma unroll
    for (int j = 0; j < 8; j++) v[j] = in[threadIdx.x + j * 256];
    float m = 0.0f;
#pragma unroll
    for (int j = 0; j < 8; j++)
        m = fmaxf(m, fmaxf(fmaxf(fabsf(v[j].x), fabsf(v[j].y)),
                           fmaxf(fabsf(v[j].z), fabsf(v[j].w))));
#pragma unroll
    for (int o = 16; o; o >>= 1) m = fmaxf(m, __shfl_xor_sync(0xffffffffu, m, o));
    __shared__ float sm[8];
    if ((threadIdx.x & 31) == 0) sm[threadIdx.x >> 5] = m;
    __syncthreads();
    if (threadIdx.x == 0) {
        float b = sm[0];
#pragma unroll
        for (int i = 1; i < 8; i++) b = fmaxf(b, sm[i]);
        atomicMax(reinterpret_cast<int*>(&g_amax_bits[which]), __float_as_int(b));
    }
}

// ---------------- phase 2: fused quantize to e4m3 codes ----------------
// nearest codebook magnitude, ties -> lower. Midpoints on |t|*scale:
//   0.25, 0.75, 1.25, 1.75, 2.5, 3.5, 5.0 ; strictly-greater moves up.
// e4m3 encodings of {0,1,2,3,4,6,8,12}: 00,38,40,44,48,4C,50,54
DINLINE uint32_t qbyte(float v, float s) {
    float a = __fmul_rn(fabsf(v), s);
    int idx = a > 5.0f  ? 7
            : a > 3.5f  ? 6
            : a > 2.5f  ? 5
            : a > 1.75f ? 4
            : a > 1.25f ? 3
            : a > 0.75f ? 2
            : a > 0.25f ? 1 : 0;
    uint32_t b = (uint32_t)((0x54504C4844403800ull >> (idx * 8)) & 0xff);
    return b | (v < 0.0f ? 0x80u : 0u);
}

__global__ void __launch_bounds__(256) quantize_kernel(const float4* __restrict__ x,
                                                       const float4* __restrict__ w) {
    const float4* in;
    uint8_t* outp;
    size_t i;
    int which;
    if (blockIdx.x < QUANT_X_BLOCKS) {
        in = x; outp = g_xq; which = 0;
        i = (size_t)blockIdx.x * 256 + threadIdx.x;
    } else {
        in = w; outp = g_wq; which = 1;
        i = (size_t)(blockIdx.x - QUANT_X_BLOCKS) * 256 + threadIdx.x;
    }
    float amax = fmaxf(__uint_as_float(g_amax_bits[which]), 1e-12f);
    float s = __fdiv_rn(6.0f, amax);

    float4 v[4];
#pragma unroll
    for (int j = 0; j < 4; j++) v[j] = in[i * 4 + j];
    uint32_t wrd[4];
#pragma unroll
    for (int j = 0; j < 4; j++) {
        wrd[j] = qbyte(v[j].x, s)
               | (qbyte(v[j].y, s) << 8)
               | (qbyte(v[j].z, s) << 16)
               | (qbyte(v[j].w, s) << 24);
    }
    reinterpret_cast<uint4*>(outp)[i] = make_uint4(wrd[0], wrd[1], wrd[2], wrd[3]);
}

// ---------------- phase 3: fp8 QMMA GEMM ----------------
// C[64,128] per CTA; 8 warps (2x4), warp tile 32x32. BK=128 -> 4 k32 steps/stage.
// Register double-buffered fragments; one barrier per 32 mma.

struct Frag { uint32_t a[2][4]; uint32_t b[2][4]; };

DINLINE void load_frags(Frag& f, uint32_t base, uint32_t ksoff,
                        const uint32_t* offA, const uint32_t* offB) {
    ldsm4(f.a[0], base + offA[0] + ksoff);
    ldsm4(f.a[1], base + offA[1] + ksoff);
    ldsm4(f.b[0], base + offB[0] + ksoff);
    ldsm4(f.b[1], base + offB[1] + ksoff);
}

DINLINE void mma_step(float acc[2][4][4], const Frag& f) {
#pragma unroll
    for (int mt = 0; mt < 2; mt++)
#pragma unroll
        for (int nt = 0; nt < 4; nt++)
            mma_f8(acc[mt][nt], f.a[mt], &f.b[nt >> 1][(nt & 1) * 2]);
}

__global__ void __launch_bounds__(256, 2) gemm_kernel(float* __restrict__ out) {
    extern __shared__ char smem[];
    uint32_t sb = smem_u32(smem);
    const int tid = threadIdx.x;
    const int lane = tid & 31, wid = tid >> 5;
    const int wm = wid >> 2, wn = wid & 3;
    const int bm = blockIdx.x & 7, bn = blockIdx.x >> 3;
    const uint8_t* Ag = g_xq + (size_t)bm * BM * K_DIM;
    const uint8_t* Bg = g_wq + (size_t)bn * BN * K_DIM;

    // cp.async mapping: 1536 x 16B chunks per stage (A 512 + B 1024), 6 per thread
    uint32_t soff[6];
    const uint8_t* gp[6];
#pragma unroll
    for (int j = 0; j < 6; j++) {
        int idx = tid + j * 256;
        if (idx < 512) {                       // A: 64 rows x 8 chunks
            int row = idx >> 3, ch = idx & 7;
            soff[j] = (uint32_t)(row * ROWB + ch * 16);
            gp[j] = Ag + (size_t)row * K_DIM + ch * 16;
        } else {                               // B: 128 rows x 8 chunks
            int r2 = idx - 512;
            int row = r2 >> 3, ch = r2 & 7;
            soff[j] = (uint32_t)(TILE_A_BYTES + row * ROWB + ch * 16);
            gp[j] = Bg + (size_t)row * K_DIM + ch * 16;
        }
    }

    // per-lane ldmatrix base offsets (ks=0); add ks*32 per k32 step
    uint32_t offA[2], offB[2];
    {
        int rA = wm * 32 + (lane & 15);
        int kA = (lane & 16);
        offA[0] = (uint32_t)(rA * ROWB + kA);
        offA[1] = (uint32_t)((rA + 16) * ROWB + kA);
        int mB = lane >> 3;
        int rB = wn * 32 + (mB >> 1) * 8 + (lane & 7);
        int kB = (mB & 1) * 16;
        offB[0] = (uint32_t)(TILE_A_BYTES + rB * ROWB + kB);
        offB[1] = (uint32_t)(TILE_A_BYTES + (rB + 16) * ROWB + kB);
    }

    float acc[2][4][4];
#pragma unroll
    for (int mt = 0; mt < 2; mt++)
#pragma unroll
        for (int nt = 0; nt < 4; nt++)
#pragma unroll
            for (int i = 0; i < 4; i++) acc[mt][nt][i] = 0.0f;

    // prologue: fill stages 0..2
#pragma unroll
    for (int s = 0; s < STAGES - 1; s++) {
#pragma unroll
        for (int j = 0; j < 6; j++) { cp16(sb + s * STAGE_BYTES + soff[j], gp[j]); gp[j] += BK; }
        cp_commit();
    }
    asm volatile("cp.async.wait_group 2;" ::: "memory");
    __syncthreads();

    Frag f0, f1;
    load_frags(f0, sb, 0, offA, offB);

    for (int k = 0; k < KIT; k++) {
        uint32_t base = sb + (uint32_t)(k & (STAGES - 1)) * STAGE_BYTES;

        // prefetch stage k+3 (slot last read in iter k-1; sync at k-1 tail ordered it)
        if (k + STAGES - 1 < KIT) {
            uint32_t sp = sb + (uint32_t)((k + STAGES - 1) & (STAGES - 1)) * STAGE_BYTES;
#pragma unroll
            for (int j = 0; j < 6; j++) { cp16(sp + soff[j], gp[j]); gp[j] += BK; }
            cp_commit();
        }

        // ks=0..2: load next frag, then mma current (latency hidden)
        load_frags(f1, base, 32, offA, offB);
        mma_step(acc, f0);
        load_frags(f0, base, 64, offA, offB);
        mma_step(acc, f1);
        load_frags(f1, base, 96, offA, offB);
        mma_step(acc, f0);
        // ks=3
        mma_step(acc, f1);

        if (k < KIT - 1) {
            // ensure stage k+1 is resident: allowed pending = min(2, KIT-2-k)
            if (k <= KIT - 4)      asm volatile("cp.async.wait_group 2;" ::: "memory");
            else if (k == KIT - 3) asm volatile("cp.async.wait_group 1;" ::: "memory");
            else                   asm volatile("cp.async.wait_group 0;" ::: "memory");
            __syncthreads();
            uint32_t nb = sb + (uint32_t)((k + 1) & (STAGES - 1)) * STAGE_BYTES;
            load_frags(f0, nb, 0, offA, offB);
        }
    }

    // epilogue: scale by inv_scale_x * inv_scale_w / 4 (codes are 2x codebook values)
    float ax = fmaxf(__uint_as_float(g_amax_bits[0]), 1e-12f);
    float aw = fmaxf(__uint_as_float(g_amax_bits[1]), 1e-12f);
    float invx = __fdiv_rn(1.0f, __fdiv_rn(6.0f, ax));
    float invw = __fdiv_rn(1.0f, __fdiv_rn(6.0f, aw));
    float scl = invx * invw * 0.25f;

    int row0 = bm * BM + wm * 32 + (lane >> 2);
    int col0 = bn * BN + wn * 32 + (lane & 3) * 2;
#pragma unroll
    for (int mt = 0; mt < 2; mt++) {
#pragma unroll
        for (int nt = 0; nt < 4; nt++) {
            float2 v0, v1;
            v0.x = acc[mt][nt][0] * scl;
            v0.y = acc[mt][nt][1] * scl;
            v1.x = acc[mt][nt][2] * scl;
            v1.y = acc[mt][nt][3] * scl;
            int r = row0 + mt * 16;
            int c = col0 + nt * 8;
            *reinterpret_cast<float2*>(out + (size_t)r * N_DIM + c) = v0;
            *reinterpret_cast<float2*>(out + (size_t)(r + 8) * N_DIM + c) = v1;
        }
    }
}

// ---------------- launch ----------------
extern "C" void kernel_launch(void* const* d_in, const int* in_sizes, int n_in,
                              void* d_out, int out_size) {
    const float* x = (const float*)d_in[0];       // [512, 4096]
    const float* w = (const float*)d_in[1];       // [4096, 4096]
    float* out = (float*)d_out;                   // [512, 4096] fp32

    cudaFuncSetAttribute(gemm_kernel, cudaFuncAttributeMaxDynamicSharedMemorySize, SMEM_TOTAL);

    init_kernel<<<1, 32>>>();
    amax_kernel<<<AMAX_X_BLOCKS + AMAX_W_BLOCKS, 256>>>((const float4*)x, (const float4*)w);
    quantize_kernel<<<QUANT_X_BLOCKS + QUANT_W_BLOCKS, 256>>>((const float4*)x, (const float4*)w);
    gemm_kernel<<<(M_DIM / BM) * (N_DIM / BN), 256, SMEM_TOTAL>>>(out);
}